// round 15
// baseline (speedup 1.0000x reference)
#include <cuda_runtime.h>
#include <math.h>
#include <stdint.h>

#define BATCH 16
#define KTOK  1024
#define DD    768
#define SEM   384
#define STRD  384
#define NB    128
#define NSTEP (KTOK/NB)
#define JP    16              // column-reduction parts
#define ROWSP (KTOK/JP)       // 64 rows per part
#define ESCW  (3*SEM)         // 1152 packed [e|s|c] row width
#define PV_SMEM ((NB*(NB+1) + NB) * 8)

#define GM_BK    32
#define GM_LDA   132
#define GM_BUF   (GM_BK*GM_LDA)            // floats per stage per array
#define GM_SMEM  (2*GM_BUF*2*4)            // bytes: 2 stages x (As+Bs)

// ---------------- device scratch (bss, no runtime allocation) ----------------
__device__ float  g_esc [(size_t)BATCH*KTOK*ESCW];   // [e | s | c] packed
__device__ float  g_di  [BATCH*KTOK*STRD];
__device__ float  g_ujk [2*BATCH*KTOK*STRD];         // u_j then u_k
__device__ float  g_v   [BATCH*KTOK*STRD];
__device__ float  g_A   [(size_t)BATCH*KTOK*KTOK];   // raw scores -> normalized A
__device__ float  g_g   [BATCH*KTOK];
__device__ float  g_cm  [BATCH*KTOK];
__device__ float  g_fid [BATCH*KTOK];
__device__ float  g_cs  [BATCH*KTOK];
__device__ float  g_pmax[JP*BATCH*KTOK];
__device__ float  g_psum[JP*BATCH*KTOK];
__device__ float  g_G   [(size_t)BATCH*KTOK*KTOK];   // Laplacian -> in-place inverse
__device__ float  g_Wf0 [BATCH*KTOK*NB];             // double-buffered W (race fix)
__device__ float  g_Wf1 [BATCH*KTOK*NB];
__device__ float  g_Pvf [BATCH*NB*NB];
__device__ float  g_Rf  [BATCH*NB*KTOK];
__device__ float  g_Wcat[2*STRD*STRD];
__device__ float  g_bcat[2*STRD];

// ---------------- cp.async helpers ----------------
__device__ __forceinline__ uint32_t smem_u32(const void* p) {
    return (uint32_t)__cvta_generic_to_shared(p);
}
__device__ __forceinline__ void cp_async4(uint32_t s, const float* g) {
    asm volatile("cp.async.ca.shared.global [%0], [%1], 4;" :: "r"(s), "l"(g));
}
__device__ __forceinline__ void cp_async16(uint32_t s, const float* g) {
    asm volatile("cp.async.cg.shared.global [%0], [%1], 16;" :: "r"(s), "l"(g));
}
__device__ __forceinline__ void cp_commit() {
    asm volatile("cp.async.commit_group;");
}
template<int N> __device__ __forceinline__ void cp_wait() {
    asm volatile("cp.async.wait_group %0;" :: "n"(N));
}

// ---------------- elementwise kernels ----------------
__global__ void split_kernel(const float* __restrict__ x,
                             float* __restrict__ esc, float* __restrict__ di) {
    int i = blockIdx.x * blockDim.x + threadIdx.x;
    if (i >= BATCH*KTOK*SEM) return;
    int c  = i % SEM;
    int bk = i / SEM;
    const float* xr = x + (size_t)bk * DD;
    esc[(size_t)bk*ESCW + c] = xr[c < 192 ? c       : c + 192];
    di[i]                    = xr[c < 192 ? c + 192 : c + 384];
}

__global__ void wcat_kernel(const float* __restrict__ Wp_w, const float* __restrict__ Wp_b,
                            const float* __restrict__ Wc_w, const float* __restrict__ Wc_b,
                            float* __restrict__ Wcat, float* __restrict__ bcat) {
    int i = blockIdx.x * blockDim.x + threadIdx.x;
    if (i < STRD*STRD) { Wcat[i] = Wp_w[i]; Wcat[STRD*STRD + i] = Wc_w[i]; }
    if (i < STRD)      { bcat[i] = Wp_b[i]; bcat[STRD + i]      = Wc_b[i]; }
}

__global__ void fi_kernel(const float* __restrict__ di,
                          const float* __restrict__ fw,
                          float* __restrict__ g) {
    int row  = blockIdx.x * 8 + (threadIdx.x >> 5);
    int lane = threadIdx.x & 31;
    if (row >= BATCH*KTOK) return;
    const float* d = di + (size_t)row * STRD;
    float s = 0.f;
    for (int c = lane; c < STRD; c += 32) s += d[c] * fw[c];
    #pragma unroll
    for (int o = 16; o; o >>= 1) s += __shfl_xor_sync(0xffffffffu, s, o);
    if (lane == 0) g[row] = s;
}

// phase 1: partial per-column max over a 64-row slab
__global__ void colmax_part_kernel(const float* __restrict__ S,
                                   float* __restrict__ pmax) {
    int i  = blockIdx.x * blockDim.x + threadIdx.x;   // (b,k)
    int jp = blockIdx.y;
    if (i >= BATCH*KTOK) return;
    int b = i / KTOK, k = i % KTOK;
    const float* Sb = S + (size_t)b*KTOK*KTOK + k;
    float m = -3.4e38f;
    int j0 = jp * ROWSP;
    #pragma unroll 4
    for (int j = j0; j < j0 + ROWSP; j++) {
        float v = Sb[(size_t)j*KTOK];
        if (j != k) m = fmaxf(m, v);
    }
    pmax[(size_t)jp*BATCH*KTOK + i] = m;
}

// phase 2: cm = max(g, partials); fid = exp(g - cm)
__global__ void colmax_reduce_kernel(const float* __restrict__ pmax,
                                     const float* __restrict__ g,
                                     float* __restrict__ cm,
                                     float* __restrict__ fid) {
    int i = blockIdx.x * blockDim.x + threadIdx.x;
    if (i >= BATCH*KTOK) return;
    float m = g[i];
    #pragma unroll
    for (int jp = 0; jp < JP; jp++)
        m = fmaxf(m, pmax[(size_t)jp*BATCH*KTOK + i]);
    cm[i]  = m;
    fid[i] = expf(g[i] - m);
}

// phase 1: normalize+exp in place, partial column sums over a 64-row slab
__global__ void normA_colsum_part_kernel(float* __restrict__ S,
                                         const float* __restrict__ cm,
                                         float* __restrict__ psum) {
    int i  = blockIdx.x * blockDim.x + threadIdx.x;
    int jp = blockIdx.y;
    if (i >= BATCH*KTOK) return;
    int b = i / KTOK, k = i % KTOK;
    float m = cm[i];
    float* Sb = S + (size_t)b*KTOK*KTOK + k;
    float s = 0.f;
    int j0 = jp * ROWSP;
    for (int j = j0; j < j0 + ROWSP; j++) {
        float a = (j == k) ? 0.f : expf(Sb[(size_t)j*KTOK] - m);
        Sb[(size_t)j*KTOK] = a;
        s += a;
    }
    psum[(size_t)jp*BATCH*KTOK + i] = s;
}

__global__ void colsum_reduce_kernel(const float* __restrict__ psum,
                                     float* __restrict__ cs) {
    int i = blockIdx.x * blockDim.x + threadIdx.x;
    if (i >= BATCH*KTOK) return;
    double s = 0.0;
    #pragma unroll
    for (int jp = 0; jp < JP; jp++)
        s += (double)psum[(size_t)jp*BATCH*KTOK + i];
    cs[i] = (float)s;
}

__global__ void build_kernel(const float* __restrict__ A,
                             const float* __restrict__ fid,
                             const float* __restrict__ cs,
                             float* __restrict__ G) {
    size_t i = (size_t)blockIdx.x * blockDim.x + threadIdx.x;
    if (i >= (size_t)BATCH*KTOK*KTOK) return;
    int k = (int)(i % KTOK);
    size_t t = i / KTOK;
    int j = (int)(t % KTOK);
    int b = (int)(t / KTOK);
    float v;
    if (j == 0) v = fid[b*KTOK + k];
    else        v = -A[i] + (j == k ? cs[b*KTOK + k] : 0.f);
    G[i] = v;
}

// W = G[:, J] - E_J  and  G[:, J] := E_J   (in-place GJ column extraction)
__global__ void copyw_kernel(float* __restrict__ G, float* __restrict__ W, int k0) {
    int i = blockIdx.x * blockDim.x + threadIdx.x;
    if (i >= BATCH*KTOK*NB) return;
    int t = i % NB;
    int r = (i / NB) % KTOK;
    int b = i / (NB*KTOK);
    size_t gi = (size_t)b*KTOK*KTOK + (size_t)r*KTOK + k0 + t;
    float w = G[gi];
    bool dg = (r == k0 + t);
    W[i]  = dg ? w - 1.f : w;
    G[gi] = dg ? 1.f : 0.f;
}

// in-smem fp64 Gauss-Jordan inversion of the 128x128 pivot block (fp32 in/out)
__global__ void pivot_inv_kernel(const float* __restrict__ G,
                                 float* __restrict__ Pinv, int k0) {
    extern __shared__ double P[];           // NB x (NB+1), then rowbuf[NB]
    double* rowbuf = P + NB*(NB+1);
    int b = blockIdx.x;
    int tid = threadIdx.x;
    const float* Gb = G + (size_t)b*KTOK*KTOK;
    for (int i = tid; i < NB*NB; i += blockDim.x) {
        int r = i >> 7, c = i & 127;
        P[r*129 + c] = (double)Gb[(size_t)(k0 + r)*KTOK + k0 + c];
    }
    __syncthreads();
    int r  = tid >> 2;                      // 512 threads -> 4 threads per row
    int c0 = (tid & 3) * 32;
    for (int j = 0; j < NB; j++) {
        double pinv = 1.0 / P[j*129 + j];
        double f    = P[r*129 + j];
        if (tid < NB) rowbuf[tid] = (tid == j) ? pinv : P[j*129 + tid] * pinv;
        __syncthreads();
        if (r == j) {
            for (int c = c0; c < c0 + 32; c++) P[j*129 + c] = rowbuf[c];
        } else {
            for (int c = c0; c < c0 + 32; c++) {
                P[r*129 + c] = (c == j) ? (-f * pinv)
                                        : fma(-f, rowbuf[c], P[r*129 + c]);
            }
        }
        __syncthreads();
    }
    for (int i = tid; i < NB*NB; i += blockDim.x) {
        int rr = i >> 7, cc = i & 127;
        Pinv[(size_t)b*NB*NB + i] = (float)P[rr*129 + cc];
    }
}

// edge marginals -> transposed store of a_ki into output buffer
__global__ void marginals_kernel(const float* __restrict__ A,
                                 const float* __restrict__ Inv,
                                 float* __restrict__ out_a) {
    __shared__ float tInv[32][33];
    __shared__ float tV[32][33];
    __shared__ float dk[32];
    int b  = blockIdx.z;
    int k0 = blockIdx.x * 32;
    int j0 = blockIdx.y * 32;
    const float* Ib = Inv + (size_t)b*KTOK*KTOK;
    const float* Ab = A   + (size_t)b*KTOK*KTOK;
    int tx = threadIdx.x, ty = threadIdx.y;
    #pragma unroll
    for (int s = 0; s < 4; s++) {
        int kk = ty + 8*s;
        tInv[kk][tx] = Ib[(size_t)(k0 + kk)*KTOK + j0 + tx];
    }
    if (ty == 0) dk[tx] = Ib[(size_t)(k0 + tx)*KTOK + k0 + tx];
    __syncthreads();
    #pragma unroll
    for (int s = 0; s < 4; s++) {
        int jj = ty + 8*s;
        int j = j0 + jj, k = k0 + tx;
        float a = Ab[(size_t)j*KTOK + k];
        float v = ((k != 0) ? a * dk[tx] : 0.f)
                - ((j != 0) ? a * tInv[tx][jj] : 0.f);
        tV[jj][tx] = v;
    }
    __syncthreads();
    #pragma unroll
    for (int s = 0; s < 4; s++) {
        int kk = ty + 8*s;
        out_a[(size_t)b*KTOK*(KTOK+1) + (size_t)(k0 + kk)*(KTOK+1) + (j0 + tx) + 1]
            = tV[tx][kk];
    }
}

__global__ void d0_kernel(const float* __restrict__ fid,
                          const float* __restrict__ Inv,
                          float* __restrict__ out_a) {
    int i = blockIdx.x * blockDim.x + threadIdx.x;
    if (i >= BATCH*KTOK) return;
    int b = i / KTOK, k = i % KTOK;
    out_a[(size_t)b*KTOK*(KTOK+1) + (size_t)k*(KTOK+1)]
        = fid[i] * Inv[(size_t)b*KTOK*KTOK + (size_t)k*KTOK];
}

// si[b,j,c] += a_ki[b,j,0] * exparam[c]   (into packed esc s-section)
__global__ void rank1_kernel(const float* __restrict__ out_a,
                             const float* __restrict__ exparam,
                             float* __restrict__ esc) {
    int i = blockIdx.x * blockDim.x + threadIdx.x;
    if (i >= BATCH*KTOK*SEM) return;
    int c  = i % SEM;
    int bj = i / SEM;
    float a0 = out_a[(size_t)bj*(KTOK+1)];
    esc[(size_t)bj*ESCW + SEM + c] += a0 * exparam[c];
}

// ---------------- 128x128x32 cp.async double-buffered fp32 GEMM ----------------
// Requires: M % 128 == 0, N % 128 == 0, K % 32 == 0 (true for all call sites).
#define FLAG_BIAS  1
#define FLAG_TANH  2

__global__ __launch_bounds__(256, 2)
void gemm_kernel(const float* __restrict__ A, const float* __restrict__ B,
                 float* __restrict__ C, const float* __restrict__ bias,
                 int M, int N, int Kd,
                 long long sAb, int sAm, int sAk,
                 long long sBb, int sBk, int sBn,
                 long long sCb, int sCm, int sBiasB,
                 float alpha, float beta, int flags) {
    extern __shared__ float sm[];
    float* AsB = sm;                 // [2][GM_BK][GM_LDA]
    float* BsB = sm + 2*GM_BUF;      // [2][GM_BK][GM_LDA]
    int bz = blockIdx.z;
    A += (size_t)bz * sAb;
    B += (size_t)bz * sBb;
    C += (size_t)bz * sCb;
    if (bias) bias += (size_t)bz * sBiasB;
    int m0 = blockIdx.y * 128, n0 = blockIdx.x * 128;
    int tid = threadIdx.x;
    int tx = tid & 15, ty = tid >> 4;

    const bool aK = (sAk == 1);   // A contiguous in K
    const bool bN = (sBn == 1);   // B contiguous in N
    const float* ga;
    const float* gb;
    long long gaStep, gbStep;
    int aM, aKb, aKr, aM8, bR, bC, bNn, bKb;
    if (aK) { aM = tid >> 1; aKb = (tid & 1) * 16;
              ga = A + (size_t)(m0 + aM) * sAm + aKb; gaStep = GM_BK; }
    else    { aKr = tid >> 4; aM8 = (tid & 15) * 8;
              ga = A + (size_t)(m0 + aM8) * sAm + (size_t)aKr * sAk;
              gaStep = (long long)GM_BK * sAk; }
    if (bN) { bR = tid >> 3; bC = (tid & 7) * 16;
              gb = B + (size_t)bR * sBk + (n0 + bC); gbStep = (long long)GM_BK * sBk; }
    else    { bNn = tid >> 1; bKb = (tid & 1) * 16;
              gb = B + (size_t)(n0 + bNn) * sBn + (size_t)bKb * sBk;
              gbStep = (long long)GM_BK * sBk; }

    auto issue = [&](int buf) {
        float* Ad = AsB + buf * GM_BUF;
        float* Bd = BsB + buf * GM_BUF;
        if (aK) {
            uint32_t s = smem_u32(Ad + aKb * GM_LDA + aM);
            #pragma unroll
            for (int i = 0; i < 16; i++) cp_async4(s + i * GM_LDA * 4, ga + i);
        } else {
            uint32_t s0 = smem_u32(Ad + aKr * GM_LDA + aM8);
            uint32_t s1 = smem_u32(Ad + (aKr + 16) * GM_LDA + aM8);
            const float* g1 = ga + (size_t)16 * sAk;
            #pragma unroll
            for (int i = 0; i < 8; i++) {
                cp_async4(s0 + i * 4, ga + (size_t)i * sAm);
                cp_async4(s1 + i * 4, g1 + (size_t)i * sAm);
            }
        }
        if (bN) {
            uint32_t s = smem_u32(Bd + bR * GM_LDA + bC);
            cp_async16(s,      gb);
            cp_async16(s + 16, gb + 4);
            cp_async16(s + 32, gb + 8);
            cp_async16(s + 48, gb + 12);
        } else {
            uint32_t s = smem_u32(Bd + bKb * GM_LDA + bNn);
            #pragma unroll
            for (int i = 0; i < 16; i++)
                cp_async4(s + i * GM_LDA * 4, gb + (size_t)i * sBk);
        }
        ga += gaStep; gb += gbStep;
        cp_commit();
    };

    float acc[8][8];
    #pragma unroll
    for (int i = 0; i < 8; i++)
        #pragma unroll
        for (int j = 0; j < 8; j++) acc[i][j] = 0.f;

    int nk = Kd >> 5;
    issue(0);
    for (int kt = 0; kt < nk; kt++) {
        int cur = kt & 1;
        if (kt + 1 < nk) { issue(cur ^ 1); cp_wait<1>(); }
        else             { cp_wait<0>(); }
        __syncthreads();
        const float* Ad = AsB + cur * GM_BUF;
        const float* Bd = BsB + cur * GM_BUF;
        #pragma unroll
        for (int kk = 0; kk < GM_BK; kk++) {
            float4 a0 = *(const float4*)(Ad + kk * GM_LDA + ty*8);
            float4 a1 = *(const float4*)(Ad + kk * GM_LDA + ty*8 + 4);
            float4 b0 = *(const float4*)(Bd + kk * GM_LDA + tx*8);
            float4 b1 = *(const float4*)(Bd + kk * GM_LDA + tx*8 + 4);
            float av[8] = {a0.x, a0.y, a0.z, a0.w, a1.x, a1.y, a1.z, a1.w};
            float bv[8] = {b0.x, b0.y, b0.z, b0.w, b1.x, b1.y, b1.z, b1.w};
            #pragma unroll
            for (int i = 0; i < 8; i++)
                #pragma unroll
                for (int j = 0; j < 8; j++)
                    acc[i][j] += av[i] * bv[j];
        }
        __syncthreads();
    }

    // ---- epilogue ----
    #pragma unroll
    for (int i = 0; i < 8; i++) {
        float* cp = C + (size_t)(m0 + ty*8 + i) * sCm + n0 + tx*8;
        #pragma unroll
        for (int g = 0; g < 2; g++) {
            float v0 = alpha * acc[i][4*g + 0];
            float v1 = alpha * acc[i][4*g + 1];
            float v2 = alpha * acc[i][4*g + 2];
            float v3 = alpha * acc[i][4*g + 3];
            if (beta != 0.f) {
                float4 o = *(const float4*)(cp + 4*g);
                v0 += beta * o.x; v1 += beta * o.y;
                v2 += beta * o.z; v3 += beta * o.w;
            }
            if (flags & FLAG_BIAS) {
                const float* bb = bias + n0 + tx*8 + 4*g;
                v0 += bb[0]; v1 += bb[1]; v2 += bb[2]; v3 += bb[3];
            }
            if (flags & FLAG_TANH) {
                v0 = tanhf(v0); v1 = tanhf(v1);
                v2 = tanhf(v2); v3 = tanhf(v3);
            }
            float4 w; w.x = v0; w.y = v1; w.z = v2; w.w = v3;
            *(float4*)(cp + 4*g) = w;
        }
    }
}

static inline void launch_gemm_s(cudaStream_t st,
                                 const float* A, const float* B, float* C,
                                 const float* bias,
                                 int M, int N, int Kd,
                                 long long sAb, int sAm, int sAk,
                                 long long sBb, int sBk, int sBn,
                                 long long sCb, int sCm, int sBiasB,
                                 float alpha, float beta, int flags, int batch) {
    dim3 g(N / 128, M / 128, batch);
    gemm_kernel<<<g, 256, GM_SMEM, st>>>(A, B, C, bias, M, N, Kd,
                                         sAb, sAm, sAk, sBb, sBk, sBn, sCb, sCm, sBiasB,
                                         alpha, beta, flags);
}
static inline void launch_gemm(const float* A, const float* B, float* C,
                               const float* bias,
                               int M, int N, int Kd,
                               long long sAb, int sAm, int sAk,
                               long long sBb, int sBk, int sBn,
                               long long sCb, int sCm, int sBiasB,
                               float alpha, float beta, int flags, int batch) {
    launch_gemm_s((cudaStream_t)0, A, B, C, bias, M, N, Kd,
                  sAb, sAm, sAk, sBb, sBk, sBn, sCb, sCm, sBiasB,
                  alpha, beta, flags, batch);
}

// ---------------- driver ----------------
extern "C" void kernel_launch(void* const* d_in, const int* in_sizes, int n_in,
                              void* d_out, int out_size) {
    const float* x       = (const float*)d_in[0];
    const float* Wp_w    = (const float*)d_in[1];
    const float* Wp_b    = (const float*)d_in[2];
    const float* Wc_w    = (const float*)d_in[3];
    const float* Wc_b    = (const float*)d_in[4];
    const float* fi_w    = (const float*)d_in[5];
    const float* Wa_w    = (const float*)d_in[6];
    const float* exparam = (const float*)d_in[7];
    const float* Wr_w    = (const float*)d_in[8];
    const float* Wr_b    = (const float*)d_in[9];

    float* out_r = (float*)d_out;
    float* out_a = out_r + (size_t)BATCH*KTOK*SEM;

    float *esc, *di, *ujk, *vv, *Am, *gg, *cm, *fid, *cs, *pmax, *psum;
    float *G, *Wf0, *Wf1, *Pvf, *Rf, *Wcat, *bcat;
    cudaGetSymbolAddress((void**)&esc,  g_esc);
    cudaGetSymbolAddress((void**)&di,   g_di);
    cudaGetSymbolAddress((void**)&ujk,  g_ujk);
    cudaGetSymbolAddress((void**)&vv,   g_v);
    cudaGetSymbolAddress((void**)&Am,   g_A);
    cudaGetSymbolAddress((void**)&gg,   g_g);
    cudaGetSymbolAddress((void**)&cm,   g_cm);
    cudaGetSymbolAddress((void**)&fid,  g_fid);
    cudaGetSymbolAddress((void**)&cs,   g_cs);
    cudaGetSymbolAddress((void**)&pmax, g_pmax);
    cudaGetSymbolAddress((void**)&psum, g_psum);
    cudaGetSymbolAddress((void**)&G,    g_G);
    cudaGetSymbolAddress((void**)&Wf0,  g_Wf0);
    cudaGetSymbolAddress((void**)&Wf1,  g_Wf1);
    cudaGetSymbolAddress((void**)&Pvf,  g_Pvf);
    cudaGetSymbolAddress((void**)&Rf,   g_Rf);
    cudaGetSymbolAddress((void**)&Wcat, g_Wcat);
    cudaGetSymbolAddress((void**)&bcat, g_bcat);

    float* uj = ujk;
    float* uk = ujk + (size_t)BATCH*KTOK*STRD;

    cudaFuncSetAttribute(pivot_inv_kernel,
                         cudaFuncAttributeMaxDynamicSharedMemorySize, PV_SMEM);
    cudaFuncSetAttribute(gemm_kernel,
                         cudaFuncAttributeMaxDynamicSharedMemorySize, GM_SMEM);

    // streams + events (created on the uncaptured correctness call; graph
    // fork/join via event record/wait is the supported capture pattern)
    static cudaStream_t s1 = nullptr, s2 = nullptr;
    static cudaEvent_t evA[NSTEP], evB[NSTEP], evR[NSTEP], evS2[NSTEP];
    static cudaEvent_t evSplit, evFi, evC, evD;
    if (!s1) {
        cudaStreamCreateWithFlags(&s1, cudaStreamNonBlocking);
        cudaStreamCreateWithFlags(&s2, cudaStreamNonBlocking);
        for (int i = 0; i < NSTEP; i++) {
            cudaEventCreateWithFlags(&evA[i],  cudaEventDisableTiming);
            cudaEventCreateWithFlags(&evB[i],  cudaEventDisableTiming);
            cudaEventCreateWithFlags(&evR[i],  cudaEventDisableTiming);
            cudaEventCreateWithFlags(&evS2[i], cudaEventDisableTiming);
        }
        cudaEventCreateWithFlags(&evSplit, cudaEventDisableTiming);
        cudaEventCreateWithFlags(&evFi,    cudaEventDisableTiming);
        cudaEventCreateWithFlags(&evC,     cudaEventDisableTiming);
        cudaEventCreateWithFlags(&evD,     cudaEventDisableTiming);
    }

    // 1) split (e into packed esc, di), weight concat; fi overlapped on s2
    split_kernel<<<(BATCH*KTOK*SEM + 255)/256, 256>>>(x, esc, di);
    cudaEventRecord(evSplit, 0);
    cudaStreamWaitEvent(s2, evSplit, 0);
    fi_kernel<<<(BATCH*KTOK + 7)/8, 256, 0, s2>>>(di, fi_w, gg);
    cudaEventRecord(evFi, s2);
    wcat_kernel<<<(STRD*STRD + 255)/256, 256>>>(Wp_w, Wp_b, Wc_w, Wc_b, Wcat, bcat);

    // 2) [u_j; u_k] = tanh(d @ [Wp; Wc] + [bp; bc])  — one batch=2 GEMM
    launch_gemm(di, Wcat, ujk, bcat, BATCH*KTOK, STRD, STRD,
                0, STRD, 1,
                (long long)STRD*STRD, STRD, 1,
                (long long)BATCH*KTOK*STRD, STRD, STRD,
                1.f, 0.f, FLAG_BIAS|FLAG_TANH, 2);

    // 3) v = u_k @ Wa^T
    launch_gemm(uk, Wa_w, vv, nullptr, BATCH*KTOK, STRD, STRD,
                0, STRD, 1, 0, 1, STRD, 0, STRD, 0, 1.f, 0.f, 0, 1);

    // 4) raw bilinear scores S = u_j v^T  (batched NT GEMM)
    launch_gemm(uj, vv, Am, nullptr, KTOK, KTOK, STRD,
                (long long)KTOK*STRD, STRD, 1,
                (long long)KTOK*STRD, 1, STRD,
                (long long)KTOK*KTOK, KTOK, 0, 1.f, 0.f, 0, BATCH);

    // 5) parallel two-phase column max / exp-normalize / column sums
    {
        dim3 gp((BATCH*KTOK + 255)/256, JP);
        colmax_part_kernel<<<gp, 256>>>(Am, pmax);
        cudaStreamWaitEvent((cudaStream_t)0, evFi, 0);   // need gg
        colmax_reduce_kernel<<<(BATCH*KTOK + 255)/256, 256>>>(pmax, gg, cm, fid);
        normA_colsum_part_kernel<<<gp, 256>>>(Am, cm, psum);
        colsum_reduce_kernel<<<(BATCH*KTOK + 255)/256, 256>>>(psum, cs);
    }

    // 6) Laplacian (fp32) into G
    build_kernel<<<(unsigned)(((size_t)BATCH*KTOK*KTOK + 255)/256), 256>>>(Am, fid, cs, G);

    // 7) in-place blocked Gauss-Jordan; pivot/copyw on s1, right-update on s2.
    //    Wf double-buffered: step s reads Wcur, copyw(s+1) writes Wnxt.
    pivot_inv_kernel<<<BATCH, 512, PV_SMEM>>>(G, Pvf, 0);
    copyw_kernel<<<(BATCH*KTOK*NB + 255)/256, 256>>>(G, Wf0, 0);
    for (int s = 0; s < NSTEP; s++) {
        int k0 = s * NB;
        float* Wcur = (s & 1) ? Wf1 : Wf0;
        float* Wnxt = (s & 1) ? Wf0 : Wf1;
        // R = Pinv @ G[J, :]   (NB x KTOK)
        launch_gemm(Pvf, G + (size_t)k0*KTOK, Rf, nullptr, NB, KTOK, NB,
                    (long long)NB*NB, NB, 1,
                    (long long)KTOK*KTOK, KTOK, 1,
                    (long long)NB*KTOK, KTOK, 0, 1.f, 0.f, 0, BATCH);
        if (s + 1 < NSTEP) {
            int kn = k0 + NB;               // next pivot block columns
            int rw = KTOK - kn - NB;
            // right-update (cols [kn+NB, KTOK)) on s2, concurrent with the rest
            cudaEventRecord(evR[s], 0);
            cudaStreamWaitEvent(s2, evR[s], 0);
            if (rw > 0) {
                launch_gemm_s(s2, Wcur, Rf + kn + NB, G + kn + NB, nullptr,
                              KTOK, rw, NB,
                              (long long)KTOK*NB, NB, 1,
                              (long long)NB*KTOK, KTOK, 1,
                              (long long)KTOK*KTOK, KTOK, 0, -1.f, 1.f, 0, BATCH);
            }
            cudaEventRecord(evS2[s], s2);
            // update next pivot columns [kn, kn+NB) on main
            launch_gemm(Wcur, Rf + kn, G + kn, nullptr, KTOK, NB, NB,
                        (long long)KTOK*NB, NB, 1,
                        (long long)NB*KTOK, KTOK, 1,
                        (long long)KTOK*KTOK, KTOK, 0, -1.f, 1.f, 0, BATCH);
            // fork: pivot_inv(next) + copyw(next -> Wnxt) on s1
            cudaEventRecord(evA[s], 0);
            cudaStreamWaitEvent(s1, evA[s], 0);
            pivot_inv_kernel<<<BATCH, 512, PV_SMEM, s1>>>(G, Pvf, kn);
            copyw_kernel<<<(BATCH*KTOK*NB + 255)/256, 256, 0, s1>>>(G, Wnxt, kn);
            cudaEventRecord(evB[s], s1);
            // left-update (cols [0, kn)) on main
            launch_gemm(Wcur, Rf, G, nullptr, KTOK, kn, NB,
                        (long long)KTOK*NB, NB, 1,
                        (long long)NB*KTOK, KTOK, 1,
                        (long long)KTOK*KTOK, KTOK, 0, -1.f, 1.f, 0, BATCH);
            // join both side streams before next step's R GEMM
            cudaStreamWaitEvent((cudaStream_t)0, evB[s], 0);
            cudaStreamWaitEvent((cudaStream_t)0, evS2[s], 0);
        } else {
            // last step: full-width update
            launch_gemm(Wcur, Rf, G, nullptr, KTOK, KTOK, NB,
                        (long long)KTOK*NB, NB, 1,
                        (long long)NB*KTOK, KTOK, 1,
                        (long long)KTOK*KTOK, KTOK, 0, -1.f, 1.f, 0, BATCH);
        }
    }

    // 8) edge marginals -> out_a (transposed), root column d0
    marginals_kernel<<<dim3(KTOK/32, KTOK/32, BATCH), dim3(32, 8)>>>(Am, G, out_a);
    d0_kernel<<<(BATCH*KTOK + 255)/256, 256>>>(fid, G, out_a);

    // 9) ci on s2 concurrent with si + rank1 on main (disjoint esc sections)
    cudaEventRecord(evC, 0);
    cudaStreamWaitEvent(s2, evC, 0);
    launch_gemm_s(s2, out_a + 1, esc, esc + 2*SEM, nullptr, KTOK, SEM, KTOK,
                  (long long)KTOK*(KTOK+1), 1, KTOK+1,
                  (long long)KTOK*ESCW, ESCW, 1,
                  (long long)KTOK*ESCW, ESCW, 0, 1.f, 0.f, 0, BATCH);
    cudaEventRecord(evD, s2);
    launch_gemm(out_a + 1, esc, esc + SEM, nullptr, KTOK, SEM, KTOK,
                (long long)KTOK*(KTOK+1), KTOK+1, 1,
                (long long)KTOK*ESCW, ESCW, 1,
                (long long)KTOK*ESCW, ESCW, 0, 1.f, 0.f, 0, BATCH);
    rank1_kernel<<<(BATCH*KTOK*SEM + 255)/256, 256>>>(out_a, exparam, esc);
    cudaStreamWaitEvent((cudaStream_t)0, evD, 0);

    // 10) r = tanh(esc @ Wr + b)  — ONE fused K=1152 GEMM
    launch_gemm(esc, Wr_w, out_r, Wr_b, BATCH*KTOK, SEM, ESCW,
                0, ESCW, 1, 0, SEM, 1, 0, SEM, 0,
                1.f, 0.f, FLAG_BIAS|FLAG_TANH, 1);
}

// round 16
// speedup vs baseline: 1.0220x; 1.0220x over previous
#include <cuda_runtime.h>
#include <math.h>
#include <stdint.h>

#define BATCH 16
#define KTOK  1024
#define DD    768
#define SEM   384
#define STRD  384
#define NB    128
#define NSTEP (KTOK/NB)
#define JP    16              // column-reduction parts
#define ROWSP (KTOK/JP)       // 64 rows per part
#define ESCW  (3*SEM)         // 1152 packed [e|s|c] row width
#define PV_SMEM ((NB*(NB+1) + NB) * 8)

#define GM_BK    32
#define GM_LDA   132
#define GM_BUF   (GM_BK*GM_LDA)            // floats per stage per array
#define GM_SMEM  (2*GM_BUF*2*4)            // bytes: 2 stages x (As+Bs)

// ---------------- device scratch (bss, no runtime allocation) ----------------
__device__ float  g_esc [(size_t)BATCH*KTOK*ESCW];   // [e | s | c] packed
__device__ float  g_di  [BATCH*KTOK*STRD];
__device__ float  g_ujk [2*BATCH*KTOK*STRD];         // u_j then u_k
__device__ float  g_v   [BATCH*KTOK*STRD];
__device__ float  g_A   [(size_t)BATCH*KTOK*KTOK];   // raw scores -> normalized A
__device__ float  g_g   [BATCH*KTOK];
__device__ float  g_cm  [BATCH*KTOK];
__device__ float  g_fid [BATCH*KTOK];
__device__ float  g_cs  [BATCH*KTOK];
__device__ float  g_pmax[JP*BATCH*KTOK];
__device__ float  g_psum[JP*BATCH*KTOK];
__device__ float  g_G   [(size_t)BATCH*KTOK*KTOK];   // Laplacian -> in-place inverse
__device__ float  g_Wf0 [BATCH*KTOK*NB];             // double-buffered W (race fix)
__device__ float  g_Wf1 [BATCH*KTOK*NB];
__device__ float  g_Pvf [BATCH*NB*NB];
__device__ float  g_Rf  [BATCH*NB*KTOK];
__device__ float  g_Wcat[2*STRD*STRD];
__device__ float  g_bcat[2*STRD];

// ---------------- cp.async helpers ----------------
__device__ __forceinline__ uint32_t smem_u32(const void* p) {
    return (uint32_t)__cvta_generic_to_shared(p);
}
__device__ __forceinline__ void cp_async4(uint32_t s, const float* g) {
    asm volatile("cp.async.ca.shared.global [%0], [%1], 4;" :: "r"(s), "l"(g));
}
__device__ __forceinline__ void cp_async16(uint32_t s, const float* g) {
    asm volatile("cp.async.cg.shared.global [%0], [%1], 16;" :: "r"(s), "l"(g));
}
__device__ __forceinline__ void cp_commit() {
    asm volatile("cp.async.commit_group;");
}
template<int N> __device__ __forceinline__ void cp_wait() {
    asm volatile("cp.async.wait_group %0;" :: "n"(N));
}

// ---------------- elementwise kernels ----------------
__global__ void split_kernel(const float* __restrict__ x,
                             float* __restrict__ esc, float* __restrict__ di) {
    int i = blockIdx.x * blockDim.x + threadIdx.x;
    if (i >= BATCH*KTOK*SEM) return;
    int c  = i % SEM;
    int bk = i / SEM;
    const float* xr = x + (size_t)bk * DD;
    esc[(size_t)bk*ESCW + c] = xr[c < 192 ? c       : c + 192];
    di[i]                    = xr[c < 192 ? c + 192 : c + 384];
}

__global__ void wcat_kernel(const float* __restrict__ Wp_w, const float* __restrict__ Wp_b,
                            const float* __restrict__ Wc_w, const float* __restrict__ Wc_b,
                            float* __restrict__ Wcat, float* __restrict__ bcat) {
    int i = blockIdx.x * blockDim.x + threadIdx.x;
    if (i < STRD*STRD) { Wcat[i] = Wp_w[i]; Wcat[STRD*STRD + i] = Wc_w[i]; }
    if (i < STRD)      { bcat[i] = Wp_b[i]; bcat[STRD + i]      = Wc_b[i]; }
}

__global__ void fi_kernel(const float* __restrict__ di,
                          const float* __restrict__ fw,
                          float* __restrict__ g) {
    int row  = blockIdx.x * 8 + (threadIdx.x >> 5);
    int lane = threadIdx.x & 31;
    if (row >= BATCH*KTOK) return;
    const float* d = di + (size_t)row * STRD;
    float s = 0.f;
    for (int c = lane; c < STRD; c += 32) s += d[c] * fw[c];
    #pragma unroll
    for (int o = 16; o; o >>= 1) s += __shfl_xor_sync(0xffffffffu, s, o);
    if (lane == 0) g[row] = s;
}

// phase 1: partial per-column max over a 64-row slab
__global__ void colmax_part_kernel(const float* __restrict__ S,
                                   float* __restrict__ pmax) {
    int i  = blockIdx.x * blockDim.x + threadIdx.x;   // (b,k)
    int jp = blockIdx.y;
    if (i >= BATCH*KTOK) return;
    int b = i / KTOK, k = i % KTOK;
    const float* Sb = S + (size_t)b*KTOK*KTOK + k;
    float m = -3.4e38f;
    int j0 = jp * ROWSP;
    #pragma unroll 4
    for (int j = j0; j < j0 + ROWSP; j++) {
        float v = Sb[(size_t)j*KTOK];
        if (j != k) m = fmaxf(m, v);
    }
    pmax[(size_t)jp*BATCH*KTOK + i] = m;
}

// phase 2: cm = max(g, partials); fid = exp(g - cm)
__global__ void colmax_reduce_kernel(const float* __restrict__ pmax,
                                     const float* __restrict__ g,
                                     float* __restrict__ cm,
                                     float* __restrict__ fid) {
    int i = blockIdx.x * blockDim.x + threadIdx.x;
    if (i >= BATCH*KTOK) return;
    float m = g[i];
    #pragma unroll
    for (int jp = 0; jp < JP; jp++)
        m = fmaxf(m, pmax[(size_t)jp*BATCH*KTOK + i]);
    cm[i]  = m;
    fid[i] = expf(g[i] - m);
}

// phase 1: normalize+exp in place, partial column sums over a 64-row slab
__global__ void normA_colsum_part_kernel(float* __restrict__ S,
                                         const float* __restrict__ cm,
                                         float* __restrict__ psum) {
    int i  = blockIdx.x * blockDim.x + threadIdx.x;
    int jp = blockIdx.y;
    if (i >= BATCH*KTOK) return;
    int b = i / KTOK, k = i % KTOK;
    float m = cm[i];
    float* Sb = S + (size_t)b*KTOK*KTOK + k;
    float s = 0.f;
    int j0 = jp * ROWSP;
    for (int j = j0; j < j0 + ROWSP; j++) {
        float a = (j == k) ? 0.f : expf(Sb[(size_t)j*KTOK] - m);
        Sb[(size_t)j*KTOK] = a;
        s += a;
    }
    psum[(size_t)jp*BATCH*KTOK + i] = s;
}

__global__ void colsum_reduce_kernel(const float* __restrict__ psum,
                                     float* __restrict__ cs) {
    int i = blockIdx.x * blockDim.x + threadIdx.x;
    if (i >= BATCH*KTOK) return;
    double s = 0.0;
    #pragma unroll
    for (int jp = 0; jp < JP; jp++)
        s += (double)psum[(size_t)jp*BATCH*KTOK + i];
    cs[i] = (float)s;
}

__global__ void build_kernel(const float* __restrict__ A,
                             const float* __restrict__ fid,
                             const float* __restrict__ cs,
                             float* __restrict__ G) {
    size_t i = (size_t)blockIdx.x * blockDim.x + threadIdx.x;
    if (i >= (size_t)BATCH*KTOK*KTOK) return;
    int k = (int)(i % KTOK);
    size_t t = i / KTOK;
    int j = (int)(t % KTOK);
    int b = (int)(t / KTOK);
    float v;
    if (j == 0) v = fid[b*KTOK + k];
    else        v = -A[i] + (j == k ? cs[b*KTOK + k] : 0.f);
    G[i] = v;
}

// W = G[:, J] - E_J  and  G[:, J] := E_J   (in-place GJ column extraction)
__global__ void copyw_kernel(float* __restrict__ G, float* __restrict__ W, int k0) {
    int i = blockIdx.x * blockDim.x + threadIdx.x;
    if (i >= BATCH*KTOK*NB) return;
    int t = i % NB;
    int r = (i / NB) % KTOK;
    int b = i / (NB*KTOK);
    size_t gi = (size_t)b*KTOK*KTOK + (size_t)r*KTOK + k0 + t;
    float w = G[gi];
    bool dg = (r == k0 + t);
    W[i]  = dg ? w - 1.f : w;
    G[gi] = dg ? 1.f : 0.f;
}

// in-smem fp64 Gauss-Jordan inversion of the 128x128 pivot block (fp32 in/out)
__global__ void pivot_inv_kernel(const float* __restrict__ G,
                                 float* __restrict__ Pinv, int k0) {
    extern __shared__ double P[];           // NB x (NB+1), then rowbuf[NB]
    double* rowbuf = P + NB*(NB+1);
    int b = blockIdx.x;
    int tid = threadIdx.x;
    const float* Gb = G + (size_t)b*KTOK*KTOK;
    for (int i = tid; i < NB*NB; i += blockDim.x) {
        int r = i >> 7, c = i & 127;
        P[r*129 + c] = (double)Gb[(size_t)(k0 + r)*KTOK + k0 + c];
    }
    __syncthreads();
    int r  = tid >> 2;                      // 512 threads -> 4 threads per row
    int c0 = (tid & 3) * 32;
    for (int j = 0; j < NB; j++) {
        double pinv = 1.0 / P[j*129 + j];
        double f    = P[r*129 + j];
        if (tid < NB) rowbuf[tid] = (tid == j) ? pinv : P[j*129 + tid] * pinv;
        __syncthreads();
        if (r == j) {
            for (int c = c0; c < c0 + 32; c++) P[j*129 + c] = rowbuf[c];
        } else {
            for (int c = c0; c < c0 + 32; c++) {
                P[r*129 + c] = (c == j) ? (-f * pinv)
                                        : fma(-f, rowbuf[c], P[r*129 + c]);
            }
        }
        __syncthreads();
    }
    for (int i = tid; i < NB*NB; i += blockDim.x) {
        int rr = i >> 7, cc = i & 127;
        Pinv[(size_t)b*NB*NB + i] = (float)P[rr*129 + cc];
    }
}

// edge marginals -> transposed store of a_ki into output buffer
__global__ void marginals_kernel(const float* __restrict__ A,
                                 const float* __restrict__ Inv,
                                 float* __restrict__ out_a) {
    __shared__ float tInv[32][33];
    __shared__ float tV[32][33];
    __shared__ float dk[32];
    int b  = blockIdx.z;
    int k0 = blockIdx.x * 32;
    int j0 = blockIdx.y * 32;
    const float* Ib = Inv + (size_t)b*KTOK*KTOK;
    const float* Ab = A   + (size_t)b*KTOK*KTOK;
    int tx = threadIdx.x, ty = threadIdx.y;
    #pragma unroll
    for (int s = 0; s < 4; s++) {
        int kk = ty + 8*s;
        tInv[kk][tx] = Ib[(size_t)(k0 + kk)*KTOK + j0 + tx];
    }
    if (ty == 0) dk[tx] = Ib[(size_t)(k0 + tx)*KTOK + k0 + tx];
    __syncthreads();
    #pragma unroll
    for (int s = 0; s < 4; s++) {
        int jj = ty + 8*s;
        int j = j0 + jj, k = k0 + tx;
        float a = Ab[(size_t)j*KTOK + k];
        float v = ((k != 0) ? a * dk[tx] : 0.f)
                - ((j != 0) ? a * tInv[tx][jj] : 0.f);
        tV[jj][tx] = v;
    }
    __syncthreads();
    #pragma unroll
    for (int s = 0; s < 4; s++) {
        int kk = ty + 8*s;
        out_a[(size_t)b*KTOK*(KTOK+1) + (size_t)(k0 + kk)*(KTOK+1) + (j0 + tx) + 1]
            = tV[tx][kk];
    }
}

__global__ void d0_kernel(const float* __restrict__ fid,
                          const float* __restrict__ Inv,
                          float* __restrict__ out_a) {
    int i = blockIdx.x * blockDim.x + threadIdx.x;
    if (i >= BATCH*KTOK) return;
    int b = i / KTOK, k = i % KTOK;
    out_a[(size_t)b*KTOK*(KTOK+1) + (size_t)k*(KTOK+1)]
        = fid[i] * Inv[(size_t)b*KTOK*KTOK + (size_t)k*KTOK];
}

// si[b,j,c] += a_ki[b,j,0] * exparam[c]   (into packed esc s-section)
__global__ void rank1_kernel(const float* __restrict__ out_a,
                             const float* __restrict__ exparam,
                             float* __restrict__ esc) {
    int i = blockIdx.x * blockDim.x + threadIdx.x;
    if (i >= BATCH*KTOK*SEM) return;
    int c  = i % SEM;
    int bj = i / SEM;
    float a0 = out_a[(size_t)bj*(KTOK+1)];
    esc[(size_t)bj*ESCW + SEM + c] += a0 * exparam[c];
}

// ---------------- 128x128x32 cp.async double-buffered fp32 GEMM ----------------
// Requires: M % 128 == 0, N % 128 == 0, K % 32 == 0 (true for all call sites).
// nskip >= 0: block-column start positions >= nskip are shifted +NB (column-skip
// remap so one launch covers the disjoint ranges [0,nskip) u [nskip+NB, ...)).
#define FLAG_BIAS  1
#define FLAG_TANH  2

__global__ __launch_bounds__(256, 2)
void gemm_kernel(const float* __restrict__ A, const float* __restrict__ B,
                 float* __restrict__ C, const float* __restrict__ bias,
                 int M, int N, int Kd,
                 long long sAb, int sAm, int sAk,
                 long long sBb, int sBk, int sBn,
                 long long sCb, int sCm, int sBiasB,
                 float alpha, float beta, int flags, int nskip) {
    extern __shared__ float sm[];
    float* AsB = sm;                 // [2][GM_BK][GM_LDA]
    float* BsB = sm + 2*GM_BUF;      // [2][GM_BK][GM_LDA]
    int bz = blockIdx.z;
    A += (size_t)bz * sAb;
    B += (size_t)bz * sBb;
    C += (size_t)bz * sCb;
    if (bias) bias += (size_t)bz * sBiasB;
    int m0 = blockIdx.y * 128, n0 = blockIdx.x * 128;
    if (nskip >= 0 && n0 >= nskip) n0 += NB;
    int tid = threadIdx.x;
    int tx = tid & 15, ty = tid >> 4;

    const bool aK = (sAk == 1);   // A contiguous in K
    const bool bN = (sBn == 1);   // B contiguous in N
    const float* ga;
    const float* gb;
    long long gaStep, gbStep;
    int aM, aKb, aKr, aM8, bR, bC, bNn, bKb;
    if (aK) { aM = tid >> 1; aKb = (tid & 1) * 16;
              ga = A + (size_t)(m0 + aM) * sAm + aKb; gaStep = GM_BK; }
    else    { aKr = tid >> 4; aM8 = (tid & 15) * 8;
              ga = A + (size_t)(m0 + aM8) * sAm + (size_t)aKr * sAk;
              gaStep = (long long)GM_BK * sAk; }
    if (bN) { bR = tid >> 3; bC = (tid & 7) * 16;
              gb = B + (size_t)bR * sBk + (n0 + bC); gbStep = (long long)GM_BK * sBk; }
    else    { bNn = tid >> 1; bKb = (tid & 1) * 16;
              gb = B + (size_t)(n0 + bNn) * sBn + (size_t)bKb * sBk;
              gbStep = (long long)GM_BK * sBk; }

    auto issue = [&](int buf) {
        float* Ad = AsB + buf * GM_BUF;
        float* Bd = BsB + buf * GM_BUF;
        if (aK) {
            uint32_t s = smem_u32(Ad + aKb * GM_LDA + aM);
            #pragma unroll
            for (int i = 0; i < 16; i++) cp_async4(s + i * GM_LDA * 4, ga + i);
        } else {
            uint32_t s0 = smem_u32(Ad + aKr * GM_LDA + aM8);
            uint32_t s1 = smem_u32(Ad + (aKr + 16) * GM_LDA + aM8);
            const float* g1 = ga + (size_t)16 * sAk;
            #pragma unroll
            for (int i = 0; i < 8; i++) {
                cp_async4(s0 + i * 4, ga + (size_t)i * sAm);
                cp_async4(s1 + i * 4, g1 + (size_t)i * sAm);
            }
        }
        if (bN) {
            uint32_t s = smem_u32(Bd + bR * GM_LDA + bC);
            cp_async16(s,      gb);
            cp_async16(s + 16, gb + 4);
            cp_async16(s + 32, gb + 8);
            cp_async16(s + 48, gb + 12);
        } else {
            uint32_t s = smem_u32(Bd + bKb * GM_LDA + bNn);
            #pragma unroll
            for (int i = 0; i < 16; i++)
                cp_async4(s + i * GM_LDA * 4, gb + (size_t)i * sBk);
        }
        ga += gaStep; gb += gbStep;
        cp_commit();
    };

    float acc[8][8];
    #pragma unroll
    for (int i = 0; i < 8; i++)
        #pragma unroll
        for (int j = 0; j < 8; j++) acc[i][j] = 0.f;

    int nk = Kd >> 5;
    issue(0);
    for (int kt = 0; kt < nk; kt++) {
        int cur = kt & 1;
        if (kt + 1 < nk) { issue(cur ^ 1); cp_wait<1>(); }
        else             { cp_wait<0>(); }
        __syncthreads();
        const float* Ad = AsB + cur * GM_BUF;
        const float* Bd = BsB + cur * GM_BUF;
        #pragma unroll
        for (int kk = 0; kk < GM_BK; kk++) {
            float4 a0 = *(const float4*)(Ad + kk * GM_LDA + ty*8);
            float4 a1 = *(const float4*)(Ad + kk * GM_LDA + ty*8 + 4);
            float4 b0 = *(const float4*)(Bd + kk * GM_LDA + tx*8);
            float4 b1 = *(const float4*)(Bd + kk * GM_LDA + tx*8 + 4);
            float av[8] = {a0.x, a0.y, a0.z, a0.w, a1.x, a1.y, a1.z, a1.w};
            float bv[8] = {b0.x, b0.y, b0.z, b0.w, b1.x, b1.y, b1.z, b1.w};
            #pragma unroll
            for (int i = 0; i < 8; i++)
                #pragma unroll
                for (int j = 0; j < 8; j++)
                    acc[i][j] += av[i] * bv[j];
        }
        __syncthreads();
    }

    // ---- epilogue ----
    #pragma unroll
    for (int i = 0; i < 8; i++) {
        float* cp = C + (size_t)(m0 + ty*8 + i) * sCm + n0 + tx*8;
        #pragma unroll
        for (int g = 0; g < 2; g++) {
            float v0 = alpha * acc[i][4*g + 0];
            float v1 = alpha * acc[i][4*g + 1];
            float v2 = alpha * acc[i][4*g + 2];
            float v3 = alpha * acc[i][4*g + 3];
            if (beta != 0.f) {
                float4 o = *(const float4*)(cp + 4*g);
                v0 += beta * o.x; v1 += beta * o.y;
                v2 += beta * o.z; v3 += beta * o.w;
            }
            if (flags & FLAG_BIAS) {
                const float* bb = bias + n0 + tx*8 + 4*g;
                v0 += bb[0]; v1 += bb[1]; v2 += bb[2]; v3 += bb[3];
            }
            if (flags & FLAG_TANH) {
                v0 = tanhf(v0); v1 = tanhf(v1);
                v2 = tanhf(v2); v3 = tanhf(v3);
            }
            float4 w; w.x = v0; w.y = v1; w.z = v2; w.w = v3;
            *(float4*)(cp + 4*g) = w;
        }
    }
}

static inline void launch_gemm_x(cudaStream_t st,
                                 const float* A, const float* B, float* C,
                                 const float* bias,
                                 int M, int N, int Kd,
                                 long long sAb, int sAm, int sAk,
                                 long long sBb, int sBk, int sBn,
                                 long long sCb, int sCm, int sBiasB,
                                 float alpha, float beta, int flags, int batch,
                                 int nskip) {
    dim3 g(N / 128, M / 128, batch);
    gemm_kernel<<<g, 256, GM_SMEM, st>>>(A, B, C, bias, M, N, Kd,
                                         sAb, sAm, sAk, sBb, sBk, sBn, sCb, sCm, sBiasB,
                                         alpha, beta, flags, nskip);
}
static inline void launch_gemm(const float* A, const float* B, float* C,
                               const float* bias,
                               int M, int N, int Kd,
                               long long sAb, int sAm, int sAk,
                               long long sBb, int sBk, int sBn,
                               long long sCb, int sCm, int sBiasB,
                               float alpha, float beta, int flags, int batch) {
    launch_gemm_x((cudaStream_t)0, A, B, C, bias, M, N, Kd,
                  sAb, sAm, sAk, sBb, sBk, sBn, sCb, sCm, sBiasB,
                  alpha, beta, flags, batch, -1);
}

// ---------------- driver ----------------
extern "C" void kernel_launch(void* const* d_in, const int* in_sizes, int n_in,
                              void* d_out, int out_size) {
    const float* x       = (const float*)d_in[0];
    const float* Wp_w    = (const float*)d_in[1];
    const float* Wp_b    = (const float*)d_in[2];
    const float* Wc_w    = (const float*)d_in[3];
    const float* Wc_b    = (const float*)d_in[4];
    const float* fi_w    = (const float*)d_in[5];
    const float* Wa_w    = (const float*)d_in[6];
    const float* exparam = (const float*)d_in[7];
    const float* Wr_w    = (const float*)d_in[8];
    const float* Wr_b    = (const float*)d_in[9];

    float* out_r = (float*)d_out;
    float* out_a = out_r + (size_t)BATCH*KTOK*SEM;

    float *esc, *di, *ujk, *vv, *Am, *gg, *cm, *fid, *cs, *pmax, *psum;
    float *G, *Wf0, *Wf1, *Pvf, *Rf, *Wcat, *bcat;
    cudaGetSymbolAddress((void**)&esc,  g_esc);
    cudaGetSymbolAddress((void**)&di,   g_di);
    cudaGetSymbolAddress((void**)&ujk,  g_ujk);
    cudaGetSymbolAddress((void**)&vv,   g_v);
    cudaGetSymbolAddress((void**)&Am,   g_A);
    cudaGetSymbolAddress((void**)&gg,   g_g);
    cudaGetSymbolAddress((void**)&cm,   g_cm);
    cudaGetSymbolAddress((void**)&fid,  g_fid);
    cudaGetSymbolAddress((void**)&cs,   g_cs);
    cudaGetSymbolAddress((void**)&pmax, g_pmax);
    cudaGetSymbolAddress((void**)&psum, g_psum);
    cudaGetSymbolAddress((void**)&G,    g_G);
    cudaGetSymbolAddress((void**)&Wf0,  g_Wf0);
    cudaGetSymbolAddress((void**)&Wf1,  g_Wf1);
    cudaGetSymbolAddress((void**)&Pvf,  g_Pvf);
    cudaGetSymbolAddress((void**)&Rf,   g_Rf);
    cudaGetSymbolAddress((void**)&Wcat, g_Wcat);
    cudaGetSymbolAddress((void**)&bcat, g_bcat);

    float* uj = ujk;
    float* uk = ujk + (size_t)BATCH*KTOK*STRD;

    cudaFuncSetAttribute(pivot_inv_kernel,
                         cudaFuncAttributeMaxDynamicSharedMemorySize, PV_SMEM);
    cudaFuncSetAttribute(gemm_kernel,
                         cudaFuncAttributeMaxDynamicSharedMemorySize, GM_SMEM);

    // streams + events (created on the uncaptured correctness call; graph
    // fork/join via event record/wait is the supported capture pattern)
    static cudaStream_t s1 = nullptr, s2 = nullptr;
    static cudaEvent_t evA[NSTEP], evB[NSTEP];
    static cudaEvent_t evSplit, evFi;
    if (!s1) {
        cudaStreamCreateWithFlags(&s1, cudaStreamNonBlocking);
        cudaStreamCreateWithFlags(&s2, cudaStreamNonBlocking);
        for (int i = 0; i < NSTEP; i++) {
            cudaEventCreateWithFlags(&evA[i], cudaEventDisableTiming);
            cudaEventCreateWithFlags(&evB[i], cudaEventDisableTiming);
        }
        cudaEventCreateWithFlags(&evSplit, cudaEventDisableTiming);
        cudaEventCreateWithFlags(&evFi,    cudaEventDisableTiming);
    }

    // 1) split (e into packed esc, di), weight concat; fi overlapped on s2
    split_kernel<<<(BATCH*KTOK*SEM + 255)/256, 256>>>(x, esc, di);
    cudaEventRecord(evSplit, 0);
    cudaStreamWaitEvent(s2, evSplit, 0);
    fi_kernel<<<(BATCH*KTOK + 7)/8, 256, 0, s2>>>(di, fi_w, gg);
    cudaEventRecord(evFi, s2);
    wcat_kernel<<<(STRD*STRD + 255)/256, 256>>>(Wp_w, Wp_b, Wc_w, Wc_b, Wcat, bcat);

    // 2) [u_j; u_k] = tanh(d @ [Wp; Wc] + [bp; bc])  — one batch=2 GEMM
    launch_gemm(di, Wcat, ujk, bcat, BATCH*KTOK, STRD, STRD,
                0, STRD, 1,
                (long long)STRD*STRD, STRD, 1,
                (long long)BATCH*KTOK*STRD, STRD, STRD,
                1.f, 0.f, FLAG_BIAS|FLAG_TANH, 2);

    // 3) v = u_k @ Wa^T
    launch_gemm(uk, Wa_w, vv, nullptr, BATCH*KTOK, STRD, STRD,
                0, STRD, 1, 0, 1, STRD, 0, STRD, 0, 1.f, 0.f, 0, 1);

    // 4) raw bilinear scores S = u_j v^T  (batched NT GEMM)
    launch_gemm(uj, vv, Am, nullptr, KTOK, KTOK, STRD,
                (long long)KTOK*STRD, STRD, 1,
                (long long)KTOK*STRD, 1, STRD,
                (long long)KTOK*KTOK, KTOK, 0, 1.f, 0.f, 0, BATCH);

    // 5) parallel two-phase column max / exp-normalize / column sums
    {
        dim3 gp((BATCH*KTOK + 255)/256, JP);
        colmax_part_kernel<<<gp, 256>>>(Am, pmax);
        cudaStreamWaitEvent((cudaStream_t)0, evFi, 0);   // need gg
        colmax_reduce_kernel<<<(BATCH*KTOK + 255)/256, 256>>>(pmax, gg, cm, fid);
        normA_colsum_part_kernel<<<gp, 256>>>(Am, cm, psum);
        colsum_reduce_kernel<<<(BATCH*KTOK + 255)/256, 256>>>(psum, cs);
    }

    // 6) Laplacian (fp32) into G
    build_kernel<<<(unsigned)(((size_t)BATCH*KTOK*KTOK + 255)/256), 256>>>(Am, fid, cs, G);

    // 7) in-place blocked Gauss-Jordan; pivot/copyw lookahead on s1.
    //    Wf double-buffered: step s reads Wcur, copyw(s+1) writes Wnxt (race fix).
    pivot_inv_kernel<<<BATCH, 512, PV_SMEM>>>(G, Pvf, 0);
    copyw_kernel<<<(BATCH*KTOK*NB + 255)/256, 256>>>(G, Wf0, 0);
    for (int s = 0; s < NSTEP; s++) {
        int k0 = s * NB;
        float* Wcur = (s & 1) ? Wf1 : Wf0;
        float* Wnxt = (s & 1) ? Wf0 : Wf1;
        // R = Pinv @ G[J, :]   (NB x KTOK)
        launch_gemm(Pvf, G + (size_t)k0*KTOK, Rf, nullptr, NB, KTOK, NB,
                    (long long)NB*NB, NB, 1,
                    (long long)KTOK*KTOK, KTOK, 1,
                    (long long)NB*KTOK, KTOK, 0, 1.f, 0.f, 0, BATCH);
        if (s + 1 < NSTEP) {
            int kn = k0 + NB;               // next pivot block columns
            // update next pivot columns [kn, kn+NB) first
            launch_gemm(Wcur, Rf + kn, G + kn, nullptr, KTOK, NB, NB,
                        (long long)KTOK*NB, NB, 1,
                        (long long)NB*KTOK, KTOK, 1,
                        (long long)KTOK*KTOK, KTOK, 0, -1.f, 1.f, 0, BATCH);
            // fork: pivot_inv(next) + copyw(next -> Wnxt) on s1
            cudaEventRecord(evA[s], 0);
            cudaStreamWaitEvent(s1, evA[s], 0);
            pivot_inv_kernel<<<BATCH, 512, PV_SMEM, s1>>>(G, Pvf, kn);
            copyw_kernel<<<(BATCH*KTOK*NB + 255)/256, 256, 0, s1>>>(G, Wnxt, kn);
            cudaEventRecord(evB[s], s1);
            // ONE merged update of all remaining columns [0,kn) u [kn+NB, KTOK)
            // via the column-skip remap (nskip = kn)
            launch_gemm_x((cudaStream_t)0, Wcur, Rf, G, nullptr,
                          KTOK, KTOK - NB, NB,
                          (long long)KTOK*NB, NB, 1,
                          (long long)NB*KTOK, KTOK, 1,
                          (long long)KTOK*KTOK, KTOK, 0,
                          -1.f, 1.f, 0, BATCH, kn);
            // join before next step's R GEMM
            cudaStreamWaitEvent((cudaStream_t)0, evB[s], 0);
        } else {
            // last step: full-width update
            launch_gemm(Wcur, Rf, G, nullptr, KTOK, KTOK, NB,
                        (long long)KTOK*NB, NB, 1,
                        (long long)NB*KTOK, KTOK, 1,
                        (long long)KTOK*KTOK, KTOK, 0, -1.f, 1.f, 0, BATCH);
        }
    }

    // 8) edge marginals -> out_a (transposed), root column d0
    marginals_kernel<<<dim3(KTOK/32, KTOK/32, BATCH), dim3(32, 8)>>>(Am, G, out_a);
    d0_kernel<<<(BATCH*KTOK + 255)/256, 256>>>(fid, G, out_a);

    // 9) si = a_ki[:,:,1:] @ e + rank1; ci = a_ik @ e (transpose read)
    launch_gemm(out_a + 1, esc, esc + SEM, nullptr, KTOK, SEM, KTOK,
                (long long)KTOK*(KTOK+1), KTOK+1, 1,
                (long long)KTOK*ESCW, ESCW, 1,
                (long long)KTOK*ESCW, ESCW, 0, 1.f, 0.f, 0, BATCH);
    rank1_kernel<<<(BATCH*KTOK*SEM + 255)/256, 256>>>(out_a, exparam, esc);
    launch_gemm(out_a + 1, esc, esc + 2*SEM, nullptr, KTOK, SEM, KTOK,
                (long long)KTOK*(KTOK+1), 1, KTOK+1,
                (long long)KTOK*ESCW, ESCW, 1,
                (long long)KTOK*ESCW, ESCW, 0, 1.f, 0.f, 0, BATCH);

    // 10) r = tanh(esc @ Wr + b)  — ONE fused K=1152 GEMM
    launch_gemm(esc, Wr_w, out_r, Wr_b, BATCH*KTOK, SEM, ESCW,
                0, ESCW, 1, 0, SEM, 1, 0, SEM, 0,
                1.f, 0.f, FLAG_BIAS|FLAG_TANH, 1);
}

// round 17
// speedup vs baseline: 1.0295x; 1.0073x over previous
#include <cuda_runtime.h>
#include <math.h>
#include <stdint.h>

#define BATCH 16
#define KTOK  1024
#define DD    768
#define SEM   384
#define STRD  384
#define NB    128
#define NSTEP (KTOK/NB)
#define JP    16              // column-reduction parts
#define ROWSP (KTOK/JP)       // 64 rows per part
#define ESCW  (3*SEM)         // 1152 packed [e|s|c] row width
#define PV_SMEM ((NB*(NB+1) + NB) * 8)

#define GM_BK    32
#define GM_LDA   132
#define GM_BUF   (GM_BK*GM_LDA)            // floats per stage per array
#define GM_SMEM  (2*GM_BUF*2*4)            // bytes: 2 stages x (As+Bs)

// ---------------- device scratch (bss, no runtime allocation) ----------------
__device__ float  g_esc [(size_t)BATCH*KTOK*ESCW];   // [e | s | c] packed
__device__ float  g_di  [BATCH*KTOK*STRD];
__device__ float  g_ujk [2*BATCH*KTOK*STRD];         // u_j then u_k
__device__ float  g_v   [BATCH*KTOK*STRD];
__device__ float  g_A   [(size_t)BATCH*KTOK*KTOK];   // raw scores -> normalized A
__device__ float  g_g   [BATCH*KTOK];
__device__ float  g_cm  [BATCH*KTOK];
__device__ float  g_fid [BATCH*KTOK];
__device__ float  g_cs  [BATCH*KTOK];
__device__ float  g_pmax[JP*BATCH*KTOK];
__device__ float  g_psum[JP*BATCH*KTOK];
__device__ float  g_G   [(size_t)BATCH*KTOK*KTOK];   // Laplacian -> in-place inverse
__device__ float  g_Wf0 [BATCH*KTOK*NB];             // double-buffered W (race fix)
__device__ float  g_Wf1 [BATCH*KTOK*NB];
__device__ float  g_Pvf [BATCH*NB*NB];
__device__ float  g_Rf  [BATCH*NB*KTOK];
__device__ float  g_Wcat[2*STRD*STRD];
__device__ float  g_bcat[2*STRD];

// ---------------- cp.async helpers ----------------
__device__ __forceinline__ uint32_t smem_u32(const void* p) {
    return (uint32_t)__cvta_generic_to_shared(p);
}
__device__ __forceinline__ void cp_async4(uint32_t s, const float* g) {
    asm volatile("cp.async.ca.shared.global [%0], [%1], 4;" :: "r"(s), "l"(g));
}
__device__ __forceinline__ void cp_async16(uint32_t s, const float* g) {
    asm volatile("cp.async.cg.shared.global [%0], [%1], 16;" :: "r"(s), "l"(g));
}
__device__ __forceinline__ void cp_commit() {
    asm volatile("cp.async.commit_group;");
}
template<int N> __device__ __forceinline__ void cp_wait() {
    asm volatile("cp.async.wait_group %0;" :: "n"(N));
}

// ---------------- elementwise kernels ----------------
__global__ void split_kernel(const float* __restrict__ x,
                             float* __restrict__ esc, float* __restrict__ di) {
    int i = blockIdx.x * blockDim.x + threadIdx.x;
    if (i >= BATCH*KTOK*SEM) return;
    int c  = i % SEM;
    int bk = i / SEM;
    const float* xr = x + (size_t)bk * DD;
    esc[(size_t)bk*ESCW + c] = xr[c < 192 ? c       : c + 192];
    di[i]                    = xr[c < 192 ? c + 192 : c + 384];
}

__global__ void wcat_kernel(const float* __restrict__ Wp_w, const float* __restrict__ Wp_b,
                            const float* __restrict__ Wc_w, const float* __restrict__ Wc_b,
                            float* __restrict__ Wcat, float* __restrict__ bcat) {
    int i = blockIdx.x * blockDim.x + threadIdx.x;
    if (i < STRD*STRD) { Wcat[i] = Wp_w[i]; Wcat[STRD*STRD + i] = Wc_w[i]; }
    if (i < STRD)      { bcat[i] = Wp_b[i]; bcat[STRD + i]      = Wc_b[i]; }
}

__global__ void fi_kernel(const float* __restrict__ di,
                          const float* __restrict__ fw,
                          float* __restrict__ g) {
    int row  = blockIdx.x * 8 + (threadIdx.x >> 5);
    int lane = threadIdx.x & 31;
    if (row >= BATCH*KTOK) return;
    const float* d = di + (size_t)row * STRD;
    float s = 0.f;
    for (int c = lane; c < STRD; c += 32) s += d[c] * fw[c];
    #pragma unroll
    for (int o = 16; o; o >>= 1) s += __shfl_xor_sync(0xffffffffu, s, o);
    if (lane == 0) g[row] = s;
}

// phase 1: partial per-column max over a 64-row slab
__global__ void colmax_part_kernel(const float* __restrict__ S,
                                   float* __restrict__ pmax) {
    int i  = blockIdx.x * blockDim.x + threadIdx.x;   // (b,k)
    int jp = blockIdx.y;
    if (i >= BATCH*KTOK) return;
    int b = i / KTOK, k = i % KTOK;
    const float* Sb = S + (size_t)b*KTOK*KTOK + k;
    float m = -3.4e38f;
    int j0 = jp * ROWSP;
    #pragma unroll 4
    for (int j = j0; j < j0 + ROWSP; j++) {
        float v = Sb[(size_t)j*KTOK];
        if (j != k) m = fmaxf(m, v);
    }
    pmax[(size_t)jp*BATCH*KTOK + i] = m;
}

// phase 2: cm = max(g, partials); fid = exp(g - cm)
__global__ void colmax_reduce_kernel(const float* __restrict__ pmax,
                                     const float* __restrict__ g,
                                     float* __restrict__ cm,
                                     float* __restrict__ fid) {
    int i = blockIdx.x * blockDim.x + threadIdx.x;
    if (i >= BATCH*KTOK) return;
    float m = g[i];
    #pragma unroll
    for (int jp = 0; jp < JP; jp++)
        m = fmaxf(m, pmax[(size_t)jp*BATCH*KTOK + i]);
    cm[i]  = m;
    fid[i] = expf(g[i] - m);
}

// phase 1: normalize+exp in place, partial column sums over a 64-row slab
__global__ void normA_colsum_part_kernel(float* __restrict__ S,
                                         const float* __restrict__ cm,
                                         float* __restrict__ psum) {
    int i  = blockIdx.x * blockDim.x + threadIdx.x;
    int jp = blockIdx.y;
    if (i >= BATCH*KTOK) return;
    int b = i / KTOK, k = i % KTOK;
    float m = cm[i];
    float* Sb = S + (size_t)b*KTOK*KTOK + k;
    float s = 0.f;
    int j0 = jp * ROWSP;
    for (int j = j0; j < j0 + ROWSP; j++) {
        float a = (j == k) ? 0.f : expf(Sb[(size_t)j*KTOK] - m);
        Sb[(size_t)j*KTOK] = a;
        s += a;
    }
    psum[(size_t)jp*BATCH*KTOK + i] = s;
}

__global__ void colsum_reduce_kernel(const float* __restrict__ psum,
                                     float* __restrict__ cs) {
    int i = blockIdx.x * blockDim.x + threadIdx.x;
    if (i >= BATCH*KTOK) return;
    double s = 0.0;
    #pragma unroll
    for (int jp = 0; jp < JP; jp++)
        s += (double)psum[(size_t)jp*BATCH*KTOK + i];
    cs[i] = (float)s;
}

__global__ void build_kernel(const float* __restrict__ A,
                             const float* __restrict__ fid,
                             const float* __restrict__ cs,
                             float* __restrict__ G) {
    size_t i = (size_t)blockIdx.x * blockDim.x + threadIdx.x;
    if (i >= (size_t)BATCH*KTOK*KTOK) return;
    int k = (int)(i % KTOK);
    size_t t = i / KTOK;
    int j = (int)(t % KTOK);
    int b = (int)(t / KTOK);
    float v;
    if (j == 0) v = fid[b*KTOK + k];
    else        v = -A[i] + (j == k ? cs[b*KTOK + k] : 0.f);
    G[i] = v;
}

// W = G[:, J] - E_J  and  G[:, J] := E_J   (in-place GJ column extraction)
__global__ void copyw_kernel(float* __restrict__ G, float* __restrict__ W, int k0) {
    int i = blockIdx.x * blockDim.x + threadIdx.x;
    if (i >= BATCH*KTOK*NB) return;
    int t = i % NB;
    int r = (i / NB) % KTOK;
    int b = i / (NB*KTOK);
    size_t gi = (size_t)b*KTOK*KTOK + (size_t)r*KTOK + k0 + t;
    float w = G[gi];
    bool dg = (r == k0 + t);
    W[i]  = dg ? w - 1.f : w;
    G[gi] = dg ? 1.f : 0.f;
}

// in-smem fp64 Gauss-Jordan inversion of the 128x128 pivot block (fp32 in/out)
__global__ void pivot_inv_kernel(const float* __restrict__ G,
                                 float* __restrict__ Pinv, int k0) {
    extern __shared__ double P[];           // NB x (NB+1), then rowbuf[NB]
    double* rowbuf = P + NB*(NB+1);
    int b = blockIdx.x;
    int tid = threadIdx.x;
    const float* Gb = G + (size_t)b*KTOK*KTOK;
    for (int i = tid; i < NB*NB; i += blockDim.x) {
        int r = i >> 7, c = i & 127;
        P[r*129 + c] = (double)Gb[(size_t)(k0 + r)*KTOK + k0 + c];
    }
    __syncthreads();
    int r  = tid >> 2;                      // 512 threads -> 4 threads per row
    int c0 = (tid & 3) * 32;
    for (int j = 0; j < NB; j++) {
        double pinv = 1.0 / P[j*129 + j];
        double f    = P[r*129 + j];
        if (tid < NB) rowbuf[tid] = (tid == j) ? pinv : P[j*129 + tid] * pinv;
        __syncthreads();
        if (r == j) {
            for (int c = c0; c < c0 + 32; c++) P[j*129 + c] = rowbuf[c];
        } else {
            for (int c = c0; c < c0 + 32; c++) {
                P[r*129 + c] = (c == j) ? (-f * pinv)
                                        : fma(-f, rowbuf[c], P[r*129 + c]);
            }
        }
        __syncthreads();
    }
    for (int i = tid; i < NB*NB; i += blockDim.x) {
        int rr = i >> 7, cc = i & 127;
        Pinv[(size_t)b*NB*NB + i] = (float)P[rr*129 + cc];
    }
}

// edge marginals -> transposed store of a_ki into output buffer
__global__ void marginals_kernel(const float* __restrict__ A,
                                 const float* __restrict__ Inv,
                                 float* __restrict__ out_a) {
    __shared__ float tInv[32][33];
    __shared__ float tV[32][33];
    __shared__ float dk[32];
    int b  = blockIdx.z;
    int k0 = blockIdx.x * 32;
    int j0 = blockIdx.y * 32;
    const float* Ib = Inv + (size_t)b*KTOK*KTOK;
    const float* Ab = A   + (size_t)b*KTOK*KTOK;
    int tx = threadIdx.x, ty = threadIdx.y;
    #pragma unroll
    for (int s = 0; s < 4; s++) {
        int kk = ty + 8*s;
        tInv[kk][tx] = Ib[(size_t)(k0 + kk)*KTOK + j0 + tx];
    }
    if (ty == 0) dk[tx] = Ib[(size_t)(k0 + tx)*KTOK + k0 + tx];
    __syncthreads();
    #pragma unroll
    for (int s = 0; s < 4; s++) {
        int jj = ty + 8*s;
        int j = j0 + jj, k = k0 + tx;
        float a = Ab[(size_t)j*KTOK + k];
        float v = ((k != 0) ? a * dk[tx] : 0.f)
                - ((j != 0) ? a * tInv[tx][jj] : 0.f);
        tV[jj][tx] = v;
    }
    __syncthreads();
    #pragma unroll
    for (int s = 0; s < 4; s++) {
        int kk = ty + 8*s;
        out_a[(size_t)b*KTOK*(KTOK+1) + (size_t)(k0 + kk)*(KTOK+1) + (j0 + tx) + 1]
            = tV[tx][kk];
    }
}

__global__ void d0_kernel(const float* __restrict__ fid,
                          const float* __restrict__ Inv,
                          float* __restrict__ out_a) {
    int i = blockIdx.x * blockDim.x + threadIdx.x;
    if (i >= BATCH*KTOK) return;
    int b = i / KTOK, k = i % KTOK;
    out_a[(size_t)b*KTOK*(KTOK+1) + (size_t)k*(KTOK+1)]
        = fid[i] * Inv[(size_t)b*KTOK*KTOK + (size_t)k*KTOK];
}

// si[b,j,c] += a_ki[b,j,0] * exparam[c]   (into packed esc s-section)
__global__ void rank1_kernel(const float* __restrict__ out_a,
                             const float* __restrict__ exparam,
                             float* __restrict__ esc) {
    int i = blockIdx.x * blockDim.x + threadIdx.x;
    if (i >= BATCH*KTOK*SEM) return;
    int c  = i % SEM;
    int bj = i / SEM;
    float a0 = out_a[(size_t)bj*(KTOK+1)];
    esc[(size_t)bj*ESCW + SEM + c] += a0 * exparam[c];
}

// ---------------- 128x128x32 cp.async fp32 GEMM with FFMA2 inner loop -------
// Requires: M % 128 == 0, N % 128 == 0, K % 32 == 0 (true for all call sites).
// nskip >= 0: block-column start positions >= nskip are shifted +NB.
// Inner loop uses packed fp32x2 FMA (fma.rn.f32x2): per-lane IEEE fp32 in the
// same k order -> bit-identical to scalar FFMA.
#define FLAG_BIAS  1
#define FLAG_TANH  2

__global__ __launch_bounds__(256, 2)
void gemm_kernel(const float* __restrict__ A, const float* __restrict__ B,
                 float* __restrict__ C, const float* __restrict__ bias,
                 int M, int N, int Kd,
                 long long sAb, int sAm, int sAk,
                 long long sBb, int sBk, int sBn,
                 long long sCb, int sCm, int sBiasB,
                 float alpha, float beta, int flags, int nskip) {
    extern __shared__ float sm[];
    float* AsB = sm;                 // [2][GM_BK][GM_LDA]
    float* BsB = sm + 2*GM_BUF;      // [2][GM_BK][GM_LDA]
    int bz = blockIdx.z;
    A += (size_t)bz * sAb;
    B += (size_t)bz * sBb;
    C += (size_t)bz * sCb;
    if (bias) bias += (size_t)bz * sBiasB;
    int m0 = blockIdx.y * 128, n0 = blockIdx.x * 128;
    if (nskip >= 0 && n0 >= nskip) n0 += NB;
    int tid = threadIdx.x;
    int tx = tid & 15, ty = tid >> 4;

    const bool aK = (sAk == 1);   // A contiguous in K
    const bool bN = (sBn == 1);   // B contiguous in N
    const float* ga;
    const float* gb;
    long long gaStep, gbStep;
    int aM, aKb, aKr, aM8, bR, bC, bNn, bKb;
    if (aK) { aM = tid >> 1; aKb = (tid & 1) * 16;
              ga = A + (size_t)(m0 + aM) * sAm + aKb; gaStep = GM_BK; }
    else    { aKr = tid >> 4; aM8 = (tid & 15) * 8;
              ga = A + (size_t)(m0 + aM8) * sAm + (size_t)aKr * sAk;
              gaStep = (long long)GM_BK * sAk; }
    if (bN) { bR = tid >> 3; bC = (tid & 7) * 16;
              gb = B + (size_t)bR * sBk + (n0 + bC); gbStep = (long long)GM_BK * sBk; }
    else    { bNn = tid >> 1; bKb = (tid & 1) * 16;
              gb = B + (size_t)(n0 + bNn) * sBn + (size_t)bKb * sBk;
              gbStep = (long long)GM_BK * sBk; }

    auto issue = [&](int buf) {
        float* Ad = AsB + buf * GM_BUF;
        float* Bd = BsB + buf * GM_BUF;
        if (aK) {
            uint32_t s = smem_u32(Ad + aKb * GM_LDA + aM);
            #pragma unroll
            for (int i = 0; i < 16; i++) cp_async4(s + i * GM_LDA * 4, ga + i);
        } else {
            uint32_t s0 = smem_u32(Ad + aKr * GM_LDA + aM8);
            uint32_t s1 = smem_u32(Ad + (aKr + 16) * GM_LDA + aM8);
            const float* g1 = ga + (size_t)16 * sAk;
            #pragma unroll
            for (int i = 0; i < 8; i++) {
                cp_async4(s0 + i * 4, ga + (size_t)i * sAm);
                cp_async4(s1 + i * 4, g1 + (size_t)i * sAm);
            }
        }
        if (bN) {
            uint32_t s = smem_u32(Bd + bR * GM_LDA + bC);
            cp_async16(s,      gb);
            cp_async16(s + 16, gb + 4);
            cp_async16(s + 32, gb + 8);
            cp_async16(s + 48, gb + 12);
        } else {
            uint32_t s = smem_u32(Bd + bKb * GM_LDA + bNn);
            #pragma unroll
            for (int i = 0; i < 16; i++)
                cp_async4(s + i * GM_LDA * 4, gb + (size_t)i * sBk);
        }
        ga += gaStep; gb += gbStep;
        cp_commit();
    };

    // packed accumulators: acc2[i][p] holds (acc[i][2p], acc[i][2p+1])
    unsigned long long acc2[8][4];
    #pragma unroll
    for (int i = 0; i < 8; i++)
        #pragma unroll
        for (int p = 0; p < 4; p++) acc2[i][p] = 0ull;

    int nk = Kd >> 5;
    issue(0);
    for (int kt = 0; kt < nk; kt++) {
        int cur = kt & 1;
        if (kt + 1 < nk) { issue(cur ^ 1); cp_wait<1>(); }
        else             { cp_wait<0>(); }
        __syncthreads();
        const float* Ad = AsB + cur * GM_BUF;
        const float* Bd = BsB + cur * GM_BUF;
        #pragma unroll
        for (int kk = 0; kk < GM_BK; kk++) {
            float4 a0 = *(const float4*)(Ad + kk * GM_LDA + ty*8);
            float4 a1 = *(const float4*)(Ad + kk * GM_LDA + ty*8 + 4);
            float av[8] = {a0.x, a0.y, a0.z, a0.w, a1.x, a1.y, a1.z, a1.w};
            unsigned long long bv2[4];
            #pragma unroll
            for (int p = 0; p < 4; p++)
                bv2[p] = *(const unsigned long long*)(Bd + kk * GM_LDA + tx*8 + 2*p);
            #pragma unroll
            for (int i = 0; i < 8; i++) {
                unsigned long long a2;
                asm("mov.b64 %0, {%1, %1};" : "=l"(a2) : "f"(av[i]));
                #pragma unroll
                for (int p = 0; p < 4; p++)
                    asm("fma.rn.f32x2 %0, %1, %2, %0;"
                        : "+l"(acc2[i][p]) : "l"(a2), "l"(bv2[p]));
            }
        }
        __syncthreads();
    }

    // unpack accumulators
    float acc[8][8];
    #pragma unroll
    for (int i = 0; i < 8; i++)
        #pragma unroll
        for (int p = 0; p < 4; p++)
            asm("mov.b64 {%0, %1}, %2;"
                : "=f"(acc[i][2*p]), "=f"(acc[i][2*p+1]) : "l"(acc2[i][p]));

    // ---- epilogue ----
    #pragma unroll
    for (int i = 0; i < 8; i++) {
        float* cp = C + (size_t)(m0 + ty*8 + i) * sCm + n0 + tx*8;
        #pragma unroll
        for (int g = 0; g < 2; g++) {
            float v0 = alpha * acc[i][4*g + 0];
            float v1 = alpha * acc[i][4*g + 1];
            float v2 = alpha * acc[i][4*g + 2];
            float v3 = alpha * acc[i][4*g + 3];
            if (beta != 0.f) {
                float4 o = *(const float4*)(cp + 4*g);
                v0 += beta * o.x; v1 += beta * o.y;
                v2 += beta * o.z; v3 += beta * o.w;
            }
            if (flags & FLAG_BIAS) {
                const float* bb = bias + n0 + tx*8 + 4*g;
                v0 += bb[0]; v1 += bb[1]; v2 += bb[2]; v3 += bb[3];
            }
            if (flags & FLAG_TANH) {
                v0 = tanhf(v0); v1 = tanhf(v1);
                v2 = tanhf(v2); v3 = tanhf(v3);
            }
            float4 w; w.x = v0; w.y = v1; w.z = v2; w.w = v3;
            *(float4*)(cp + 4*g) = w;
        }
    }
}

static inline void launch_gemm_x(cudaStream_t st,
                                 const float* A, const float* B, float* C,
                                 const float* bias,
                                 int M, int N, int Kd,
                                 long long sAb, int sAm, int sAk,
                                 long long sBb, int sBk, int sBn,
                                 long long sCb, int sCm, int sBiasB,
                                 float alpha, float beta, int flags, int batch,
                                 int nskip) {
    dim3 g(N / 128, M / 128, batch);
    gemm_kernel<<<g, 256, GM_SMEM, st>>>(A, B, C, bias, M, N, Kd,
                                         sAb, sAm, sAk, sBb, sBk, sBn, sCb, sCm, sBiasB,
                                         alpha, beta, flags, nskip);
}
static inline void launch_gemm(const float* A, const float* B, float* C,
                               const float* bias,
                               int M, int N, int Kd,
                               long long sAb, int sAm, int sAk,
                               long long sBb, int sBk, int sBn,
                               long long sCb, int sCm, int sBiasB,
                               float alpha, float beta, int flags, int batch) {
    launch_gemm_x((cudaStream_t)0, A, B, C, bias, M, N, Kd,
                  sAb, sAm, sAk, sBb, sBk, sBn, sCb, sCm, sBiasB,
                  alpha, beta, flags, batch, -1);
}

// ---------------- driver ----------------
extern "C" void kernel_launch(void* const* d_in, const int* in_sizes, int n_in,
                              void* d_out, int out_size) {
    const float* x       = (const float*)d_in[0];
    const float* Wp_w    = (const float*)d_in[1];
    const float* Wp_b    = (const float*)d_in[2];
    const float* Wc_w    = (const float*)d_in[3];
    const float* Wc_b    = (const float*)d_in[4];
    const float* fi_w    = (const float*)d_in[5];
    const float* Wa_w    = (const float*)d_in[6];
    const float* exparam = (const float*)d_in[7];
    const float* Wr_w    = (const float*)d_in[8];
    const float* Wr_b    = (const float*)d_in[9];

    float* out_r = (float*)d_out;
    float* out_a = out_r + (size_t)BATCH*KTOK*SEM;

    float *esc, *di, *ujk, *vv, *Am, *gg, *cm, *fid, *cs, *pmax, *psum;
    float *G, *Wf0, *Wf1, *Pvf, *Rf, *Wcat, *bcat;
    cudaGetSymbolAddress((void**)&esc,  g_esc);
    cudaGetSymbolAddress((void**)&di,   g_di);
    cudaGetSymbolAddress((void**)&ujk,  g_ujk);
    cudaGetSymbolAddress((void**)&vv,   g_v);
    cudaGetSymbolAddress((void**)&Am,   g_A);
    cudaGetSymbolAddress((void**)&gg,   g_g);
    cudaGetSymbolAddress((void**)&cm,   g_cm);
    cudaGetSymbolAddress((void**)&fid,  g_fid);
    cudaGetSymbolAddress((void**)&cs,   g_cs);
    cudaGetSymbolAddress((void**)&pmax, g_pmax);
    cudaGetSymbolAddress((void**)&psum, g_psum);
    cudaGetSymbolAddress((void**)&G,    g_G);
    cudaGetSymbolAddress((void**)&Wf0,  g_Wf0);
    cudaGetSymbolAddress((void**)&Wf1,  g_Wf1);
    cudaGetSymbolAddress((void**)&Pvf,  g_Pvf);
    cudaGetSymbolAddress((void**)&Rf,   g_Rf);
    cudaGetSymbolAddress((void**)&Wcat, g_Wcat);
    cudaGetSymbolAddress((void**)&bcat, g_bcat);

    float* uj = ujk;
    float* uk = ujk + (size_t)BATCH*KTOK*STRD;

    cudaFuncSetAttribute(pivot_inv_kernel,
                         cudaFuncAttributeMaxDynamicSharedMemorySize, PV_SMEM);
    cudaFuncSetAttribute(gemm_kernel,
                         cudaFuncAttributeMaxDynamicSharedMemorySize, GM_SMEM);

    // streams + events (created on the uncaptured correctness call; graph
    // fork/join via event record/wait is the supported capture pattern)
    static cudaStream_t s1 = nullptr, s2 = nullptr;
    static cudaEvent_t evA[NSTEP], evB[NSTEP];
    static cudaEvent_t evSplit, evFi;
    if (!s1) {
        cudaStreamCreateWithFlags(&s1, cudaStreamNonBlocking);
        cudaStreamCreateWithFlags(&s2, cudaStreamNonBlocking);
        for (int i = 0; i < NSTEP; i++) {
            cudaEventCreateWithFlags(&evA[i], cudaEventDisableTiming);
            cudaEventCreateWithFlags(&evB[i], cudaEventDisableTiming);
        }
        cudaEventCreateWithFlags(&evSplit, cudaEventDisableTiming);
        cudaEventCreateWithFlags(&evFi,    cudaEventDisableTiming);
    }

    // 1) split (e into packed esc, di), weight concat; fi overlapped on s2
    split_kernel<<<(BATCH*KTOK*SEM + 255)/256, 256>>>(x, esc, di);
    cudaEventRecord(evSplit, 0);
    cudaStreamWaitEvent(s2, evSplit, 0);
    fi_kernel<<<(BATCH*KTOK + 7)/8, 256, 0, s2>>>(di, fi_w, gg);
    cudaEventRecord(evFi, s2);
    wcat_kernel<<<(STRD*STRD + 255)/256, 256>>>(Wp_w, Wp_b, Wc_w, Wc_b, Wcat, bcat);

    // 2) [u_j; u_k] = tanh(d @ [Wp; Wc] + [bp; bc])  — one batch=2 GEMM
    launch_gemm(di, Wcat, ujk, bcat, BATCH*KTOK, STRD, STRD,
                0, STRD, 1,
                (long long)STRD*STRD, STRD, 1,
                (long long)BATCH*KTOK*STRD, STRD, STRD,
                1.f, 0.f, FLAG_BIAS|FLAG_TANH, 2);

    // 3) v = u_k @ Wa^T
    launch_gemm(uk, Wa_w, vv, nullptr, BATCH*KTOK, STRD, STRD,
                0, STRD, 1, 0, 1, STRD, 0, STRD, 0, 1.f, 0.f, 0, 1);

    // 4) raw bilinear scores S = u_j v^T  (batched NT GEMM)
    launch_gemm(uj, vv, Am, nullptr, KTOK, KTOK, STRD,
                (long long)KTOK*STRD, STRD, 1,
                (long long)KTOK*STRD, 1, STRD,
                (long long)KTOK*KTOK, KTOK, 0, 1.f, 0.f, 0, BATCH);

    // 5) parallel two-phase column max / exp-normalize / column sums
    {
        dim3 gp((BATCH*KTOK + 255)/256, JP);
        colmax_part_kernel<<<gp, 256>>>(Am, pmax);
        cudaStreamWaitEvent((cudaStream_t)0, evFi, 0);   // need gg
        colmax_reduce_kernel<<<(BATCH*KTOK + 255)/256, 256>>>(pmax, gg, cm, fid);
        normA_colsum_part_kernel<<<gp, 256>>>(Am, cm, psum);
        colsum_reduce_kernel<<<(BATCH*KTOK + 255)/256, 256>>>(psum, cs);
    }

    // 6) Laplacian (fp32) into G
    build_kernel<<<(unsigned)(((size_t)BATCH*KTOK*KTOK + 255)/256), 256>>>(Am, fid, cs, G);

    // 7) in-place blocked Gauss-Jordan; pivot/copyw lookahead on s1.
    //    Wf double-buffered: step s reads Wcur, copyw(s+1) writes Wnxt (race fix).
    pivot_inv_kernel<<<BATCH, 512, PV_SMEM>>>(G, Pvf, 0);
    copyw_kernel<<<(BATCH*KTOK*NB + 255)/256, 256>>>(G, Wf0, 0);
    for (int s = 0; s < NSTEP; s++) {
        int k0 = s * NB;
        float* Wcur = (s & 1) ? Wf1 : Wf0;
        float* Wnxt = (s & 1) ? Wf0 : Wf1;
        // R = Pinv @ G[J, :]   (NB x KTOK)
        launch_gemm(Pvf, G + (size_t)k0*KTOK, Rf, nullptr, NB, KTOK, NB,
                    (long long)NB*NB, NB, 1,
                    (long long)KTOK*KTOK, KTOK, 1,
                    (long long)NB*KTOK, KTOK, 0, 1.f, 0.f, 0, BATCH);
        if (s + 1 < NSTEP) {
            int kn = k0 + NB;               // next pivot block columns
            // update next pivot columns [kn, kn+NB) first
            launch_gemm(Wcur, Rf + kn, G + kn, nullptr, KTOK, NB, NB,
                        (long long)KTOK*NB, NB, 1,
                        (long long)NB*KTOK, KTOK, 1,
                        (long long)KTOK*KTOK, KTOK, 0, -1.f, 1.f, 0, BATCH);
            // fork: pivot_inv(next) + copyw(next -> Wnxt) on s1
            cudaEventRecord(evA[s], 0);
            cudaStreamWaitEvent(s1, evA[s], 0);
            pivot_inv_kernel<<<BATCH, 512, PV_SMEM, s1>>>(G, Pvf, kn);
            copyw_kernel<<<(BATCH*KTOK*NB + 255)/256, 256, 0, s1>>>(G, Wnxt, kn);
            cudaEventRecord(evB[s], s1);
            // ONE merged update of all remaining columns [0,kn) u [kn+NB, KTOK)
            launch_gemm_x((cudaStream_t)0, Wcur, Rf, G, nullptr,
                          KTOK, KTOK - NB, NB,
                          (long long)KTOK*NB, NB, 1,
                          (long long)NB*KTOK, KTOK, 1,
                          (long long)KTOK*KTOK, KTOK, 0,
                          -1.f, 1.f, 0, BATCH, kn);
            // join before next step's R GEMM
            cudaStreamWaitEvent((cudaStream_t)0, evB[s], 0);
        } else {
            // last step: full-width update
            launch_gemm(Wcur, Rf, G, nullptr, KTOK, KTOK, NB,
                        (long long)KTOK*NB, NB, 1,
                        (long long)NB*KTOK, KTOK, 1,
                        (long long)KTOK*KTOK, KTOK, 0, -1.f, 1.f, 0, BATCH);
        }
    }

    // 8) edge marginals -> out_a (transposed), root column d0
    marginals_kernel<<<dim3(KTOK/32, KTOK/32, BATCH), dim3(32, 8)>>>(Am, G, out_a);
    d0_kernel<<<(BATCH*KTOK + 255)/256, 256>>>(fid, G, out_a);

    // 9) si = a_ki[:,:,1:] @ e + rank1; ci = a_ik @ e (transpose read)
    launch_gemm(out_a + 1, esc, esc + SEM, nullptr, KTOK, SEM, KTOK,
                (long long)KTOK*(KTOK+1), KTOK+1, 1,
                (long long)KTOK*ESCW, ESCW, 1,
                (long long)KTOK*ESCW, ESCW, 0, 1.f, 0.f, 0, BATCH);
    rank1_kernel<<<(BATCH*KTOK*SEM + 255)/256, 256>>>(out_a, exparam, esc);
    launch_gemm(out_a + 1, esc, esc + 2*SEM, nullptr, KTOK, SEM, KTOK,
                (long long)KTOK*(KTOK+1), 1, KTOK+1,
                (long long)KTOK*ESCW, ESCW, 1,
                (long long)KTOK*ESCW, ESCW, 0, 1.f, 0.f, 0, BATCH);

    // 10) r = tanh(esc @ Wr + b)  — ONE fused K=1152 GEMM
    launch_gemm(esc, Wr_w, out_r, Wr_b, BATCH*KTOK, SEM, ESCW,
                0, ESCW, 1, 0, SEM, 1, 0, SEM, 0,
                1.f, 0.f, FLAG_BIAS|FLAG_TANH, 1);
}